// round 11
// baseline (speedup 1.0000x reference)
#include <cuda_runtime.h>
#include <cuda_fp16.h>
#include <cstdint>

#define T_DIM 8192
#define K_DIM 4096
#define N_DIM 4096
#define R_DIM 64
#define NGRP  8

// ---------------- static device scratch (alloc forbidden) -------------------
__device__ __half g_x16[(size_t)T_DIM * K_DIM];
__device__ __half g_w16[(size_t)N_DIM * K_DIM];
__device__ __half g_la16[(size_t)NGRP * R_DIM * K_DIM];
__device__ __half g_lb16[(size_t)NGRP * N_DIM * R_DIM];   // [g][n][r] transposed
__device__ __half g_sh16[(size_t)T_DIM * R_DIM];

// ---------------- asm helpers (base ISA only: sm_80-class) ------------------
__device__ __forceinline__ uint32_t smem_u32(const void* p) {
    uint32_t a;
    asm("{ .reg .u64 t; cvta.to.shared.u64 t, %1; cvt.u32.u64 %0, t; }"
        : "=r"(a) : "l"(p));
    return a;
}
#define CP16(dst, src) \
    asm volatile("cp.async.cg.shared.global [%0], [%1], 16;" :: "r"(dst), "l"(src))
#define CP_COMMIT() asm volatile("cp.async.commit_group;" ::: "memory")
#define CP_WAIT1()  asm volatile("cp.async.wait_group 1;"  ::: "memory")
#define CP_WAIT2()  asm volatile("cp.async.wait_group 2;"  ::: "memory")

#define LDSM4(d, addr) \
    asm volatile("ldmatrix.sync.aligned.m8n8.x4.shared.b16 {%0,%1,%2,%3}, [%4];" \
        : "=r"((d)[0]), "=r"((d)[1]), "=r"((d)[2]), "=r"((d)[3]) : "r"(addr))

#define MMA_F16(ac, a, b0, b1) \
    asm volatile("mma.sync.aligned.m16n8k16.row.col.f32.f16.f16.f32 " \
        "{%0,%1,%2,%3}, {%4,%5,%6,%7}, {%8,%9}, {%0,%1,%2,%3};" \
        : "+f"((ac)[0]), "+f"((ac)[1]), "+f"((ac)[2]), "+f"((ac)[3]) \
        : "r"((a)[0]), "r"((a)[1]), "r"((a)[2]), "r"((a)[3]), "r"(b0), "r"(b1))

// XOR swizzle (still used by the small shrink kernel's 128B-row tiles).
__device__ __forceinline__ uint32_t swz(int row, int ch) {
    return (uint32_t)((row << 7) | (((ch ^ (row & 7)) & 7) << 4));
}

__device__ __forceinline__ int find_group(const int* __restrict__ gl,
                                          int n_groups, int token) {
    int g = 0;
    while (g < n_groups - 1 && token >= gl[g]) g++;
    return g;
}

// ---------------- pre-pass kernels ------------------------------------------
#define NX4 ((size_t)T_DIM * K_DIM / 4)
#define NW4 ((size_t)N_DIM * K_DIM / 4)
#define NL4 ((size_t)NGRP * R_DIM * K_DIM / 4)

__global__ __launch_bounds__(256) void cvt_all_kernel(
    const float* __restrict__ x, const float* __restrict__ W,
    const float* __restrict__ la)
{
    size_t i = (size_t)blockIdx.x * 256 + threadIdx.x;
    const float* src;
    __half2* dst;
    size_t j;
    if (i < NX4) {
        src = x; dst = reinterpret_cast<__half2*>(g_x16); j = i;
    } else if (i < NX4 + NW4) {
        src = W; dst = reinterpret_cast<__half2*>(g_w16); j = i - NX4;
    } else {
        src = la; dst = reinterpret_cast<__half2*>(g_la16); j = i - NX4 - NW4;
    }
    float4 v = reinterpret_cast<const float4*>(src)[j];
    dst[2 * j]     = __floats2half2_rn(v.x, v.y);
    dst[2 * j + 1] = __floats2half2_rn(v.z, v.w);
}

// transpose lora_b[g][r][n] -> [g][n][r] fp16
__global__ __launch_bounds__(256) void lorab_t_kernel(const float* __restrict__ lb) {
    __shared__ float t[64][65];
    int g = blockIdx.y;
    int n0 = blockIdx.x * 64;
    for (int idx = threadIdx.x; idx < 4096; idx += 256) {
        int r = idx >> 6, n = idx & 63;
        t[n][r] = lb[((size_t)g * R_DIM + r) * N_DIM + n0 + n];
    }
    __syncthreads();
    for (int idx = threadIdx.x; idx < 4096; idx += 256) {
        int n = idx >> 6, r = idx & 63;
        g_lb16[((size_t)g * N_DIM + n0 + n) * R_DIM + r] = __float2half_rn(t[n][r]);
    }
}

// =============================================================================
// Shrink GEMM: shrink[8192,64] = x @ lora_a[g]^T, single fp16 term.
// CTA tile 128x64, 256 threads (8 warps: 4m x 2n, warp tile 32x32), BK=64.
// (unchanged from R10 — ~40us, not worth churn)
// =============================================================================
#define SH_STAGE 24576
#define SH_CHUNKS (K_DIM / 64)   // 64

__global__ __launch_bounds__(256, 1) void shrink_gemm(
    const int* __restrict__ gl, int n_groups)
{
    extern __shared__ char smem[];
    uint32_t sb = smem_u32(smem);
    int tid = threadIdx.x, lane = tid & 31, w = tid >> 5;
    int m_off = (w & 3) * 32, n_off = (w >> 2) * 32;
    int row0 = blockIdx.x * 128;
    int g = find_group(gl, n_groups, row0);

    const __half* A = g_x16 + (size_t)row0 * K_DIM;
    const __half* B = g_la16 + (size_t)g * R_DIM * K_DIM;

    float acc[2][4][4];
    #pragma unroll
    for (int i = 0; i < 2; i++)
        #pragma unroll
        for (int j = 0; j < 4; j++)
            #pragma unroll
            for (int q = 0; q < 4; q++) acc[i][j][q] = 0.f;

    auto fill = [&](int s, int c) {
        uint32_t st = sb + s * SH_STAGE;
        #pragma unroll
        for (int it = 0; it < 6; it++) {
            int idx = tid + it * 256;
            if (idx < 1024) {
                int row = idx >> 3, ch = idx & 7;
                CP16(st + swz(row, ch),
                     A + (size_t)row * K_DIM + c * 64 + ch * 8);
            } else {
                int u = idx - 1024;
                int row = u >> 3, ch = u & 7;
                CP16(st + 16384 + swz(row, ch),
                     B + (size_t)row * K_DIM + c * 64 + ch * 8);
            }
        }
    };

    fill(0, 0); CP_COMMIT();
    fill(1, 1); CP_COMMIT();
    fill(2, 2); CP_COMMIT();

    for (int c = 0; c < SH_CHUNKS; c++) {
        CP_WAIT2();
        __syncthreads();
        uint32_t st = sb + (c & 3) * SH_STAGE;
        #pragma unroll
        for (int ks = 0; ks < 4; ks++) {
            uint32_t aa[2][4], bb[2][4];
            #pragma unroll
            for (int mt = 0; mt < 2; mt++) {
                int row = m_off + mt * 16 + (lane & 15);
                int ch = ks * 2 + (lane >> 4);
                LDSM4(aa[mt], st + swz(row, ch));
            }
            #pragma unroll
            for (int p = 0; p < 2; p++) {
                int row = n_off + p * 16 + (lane & 15);
                int ch = ks * 2 + (lane >> 4);
                LDSM4(bb[p], st + 16384 + swz(row, ch));
            }
            #pragma unroll
            for (int mt = 0; mt < 2; mt++)
                #pragma unroll
                for (int p = 0; p < 2; p++) {
                    MMA_F16(acc[mt][2 * p],     aa[mt], bb[p][0], bb[p][2]);
                    MMA_F16(acc[mt][2 * p + 1], aa[mt], bb[p][1], bb[p][3]);
                }
        }
        if (c + 3 < SH_CHUNKS) fill((c + 3) & 3, c + 3);
        CP_COMMIT();
    }

    #pragma unroll
    for (int mt = 0; mt < 2; mt++)
        #pragma unroll
        for (int j = 0; j < 4; j++) {
            int row = row0 + m_off + mt * 16 + (lane >> 2);
            int col = n_off + j * 8 + ((lane & 3) << 1);
            *reinterpret_cast<__half2*>(g_sh16 + (size_t)row * R_DIM + col)
                = __floats2half2_rn(acc[mt][j][0], acc[mt][j][1]);
            *reinterpret_cast<__half2*>(g_sh16 + (size_t)(row + 8) * R_DIM + col)
                = __floats2half2_rn(acc[mt][j][2], acc[mt][j][3]);
        }
}

// =============================================================================
// Main GEMM: out[8192,4096] = x @ W^T (+ fused LoRA expand over rank 64).
// R11: CTA 128x128, 256 thr (8 warps 4m x 2n, warp tile 32x64), BK=64,
// 3 stages, 2 CTAs/SM. PADDED smem layout (row stride 144B: 144/16 = 9 == 1
// mod 8 -> ldmatrix conflict-free without XOR): every LDSM address is
// stage_base + hoisted per-thread offset + ks*32 — kills the IMAD/LOP3
// address math that ate 31% of issue slots in R10's profile.
// =============================================================================
#define MN_RS    144                    // padded row stride (bytes)
#define MN_ATILE (128 * MN_RS)          // 18432
#define MN_STG   (2 * MN_ATILE)         // 36864 per stage; x3 = 110592/CTA
#define MN_CHUNKS (K_DIM / 64 + 1)      // 65

__global__ __launch_bounds__(256, 2) void gemm_main(
    const int* __restrict__ gl, int n_groups, float* __restrict__ out)
{
    extern __shared__ char smem[];
    uint32_t sb = smem_u32(smem);
    int tid = threadIdx.x, lane = tid & 31, w = tid >> 5;
    int m_off = (w & 3) * 32, n_off = (w >> 2) * 64;
    int row0 = blockIdx.y * 128;
    int col0 = blockIdx.x * 128;
    int g = find_group(gl, n_groups, row0);

    float acc[2][8][4];
    #pragma unroll
    for (int i = 0; i < 2; i++)
        #pragma unroll
        for (int j = 0; j < 8; j++)
            #pragma unroll
            for (int q = 0; q < 4; q++) acc[i][j][q] = 0.f;

    // hoisted per-thread LDSM offsets (relative to stage base); +ks*32 per step
    uint32_t a_off[2], b_off[4];
    {
        int lr = lane & 15, par = (lane >> 4) * 16;
        #pragma unroll
        for (int mt = 0; mt < 2; mt++)
            a_off[mt] = (uint32_t)((m_off + mt * 16 + lr) * MN_RS + par);
        #pragma unroll
        for (int p = 0; p < 4; p++)
            b_off[p] = (uint32_t)(MN_ATILE + (n_off + p * 16 + lr) * MN_RS + par);
    }

    auto fill = [&](uint32_t st, int c) {
        const __half *pA, *pB;
        size_t lda, ldb;
        if (c < K_DIM / 64) {
            pA = g_x16 + (size_t)row0 * K_DIM + c * 64;
            pB = g_w16 + (size_t)col0 * K_DIM + c * 64;
            lda = K_DIM; ldb = K_DIM;
        } else {
            pA = g_sh16 + (size_t)row0 * R_DIM;
            pB = g_lb16 + ((size_t)g * N_DIM + col0) * R_DIM;
            lda = R_DIM; ldb = R_DIM;
        }
        #pragma unroll
        for (int it = 0; it < 8; it++) {
            int idx = tid + it * 256;
            if (idx < 1024) {               // A: 128 rows x 8 ch
                int row = idx >> 3, ch = idx & 7;
                CP16(st + row * MN_RS + ch * 16, pA + (size_t)row * lda + ch * 8);
            } else {                        // B: 128 rows x 8 ch
                int u = idx - 1024;
                int row = u >> 3, ch = u & 7;
                CP16(st + MN_ATILE + row * MN_RS + ch * 16,
                     pB + (size_t)row * ldb + ch * 8);
            }
        }
    };

    fill(sb, 0);           CP_COMMIT();
    fill(sb + MN_STG, 1);  CP_COMMIT();

    uint32_t st  = sb;                       // compute stage base
    uint32_t stf = sb + 2u * MN_STG;         // fill stage base
    const uint32_t st_top = sb + 2u * MN_STG;

    for (int c = 0; c < MN_CHUNKS; c++) {
        CP_WAIT1();
        __syncthreads();
        #pragma unroll
        for (int ks = 0; ks < 4; ks++) {
            uint32_t aa[2][4], bb[4][4];
            #pragma unroll
            for (int mt = 0; mt < 2; mt++)
                LDSM4(aa[mt], st + a_off[mt] + ks * 32);
            #pragma unroll
            for (int p = 0; p < 4; p++)
                LDSM4(bb[p], st + b_off[p] + ks * 32);
            #pragma unroll
            for (int mt = 0; mt < 2; mt++)
                #pragma unroll
                for (int p = 0; p < 4; p++) {
                    MMA_F16(acc[mt][2 * p],     aa[mt], bb[p][0], bb[p][2]);
                    MMA_F16(acc[mt][2 * p + 1], aa[mt], bb[p][1], bb[p][3]);
                }
        }
        if (c + 2 < MN_CHUNKS) fill(stf, c + 2);
        CP_COMMIT();
        st  = (st  == st_top) ? sb : st  + MN_STG;
        stf = (stf == st_top) ? sb : stf + MN_STG;
    }

    #pragma unroll
    for (int mt = 0; mt < 2; mt++)
        #pragma unroll
        for (int j = 0; j < 8; j++) {
            int row = row0 + m_off + mt * 16 + (lane >> 2);
            int col = col0 + n_off + j * 8 + ((lane & 3) << 1);
            *reinterpret_cast<float2*>(out + (size_t)row * N_DIM + col)
                = make_float2(acc[mt][j][0], acc[mt][j][1]);
            *reinterpret_cast<float2*>(out + (size_t)(row + 8) * N_DIM + col)
                = make_float2(acc[mt][j][2], acc[mt][j][3]);
        }
}

// ---------------- launch -----------------------------------------------------
extern "C" void kernel_launch(void* const* d_in, const int* in_sizes, int n_in,
                              void* d_out, int out_size) {
    const float* x      = (const float*)d_in[0];
    const float* W      = (const float*)d_in[1];
    const float* lora_a = (const float*)d_in[2];
    const float* lora_b = (const float*)d_in[3];
    const int*   gl     = (const int*)d_in[4];
    const int n_groups  = in_sizes[4];
    float* out = (float*)d_out;

    cudaFuncSetAttribute(shrink_gemm, cudaFuncAttributeMaxDynamicSharedMemorySize,
                         4 * SH_STAGE);
    cudaFuncSetAttribute(gemm_main, cudaFuncAttributeMaxDynamicSharedMemorySize,
                         3 * MN_STG);

    // launch order: cvt_all(0), lorab(1), shrink(2), gemm_main(3)
    cvt_all_kernel<<<(unsigned)((NX4 + NW4 + NL4) / 256), 256>>>(x, W, lora_a);
    lorab_t_kernel<<<dim3(N_DIM / 64, NGRP), 256>>>(lora_b);
    shrink_gemm<<<T_DIM / 128, 256, 4 * SH_STAGE>>>(gl, n_groups);
    gemm_main<<<dim3(N_DIM / 128, T_DIM / 128), 256, 3 * MN_STG>>>(
        gl, n_groups, out);
}

// round 12
// speedup vs baseline: 1.0277x; 1.0277x over previous
#include <cuda_runtime.h>
#include <cuda_fp16.h>
#include <cstdint>

#define T_DIM 8192
#define K_DIM 4096
#define N_DIM 4096
#define R_DIM 64
#define NGRP  8

// ---------------- static device scratch (alloc forbidden) -------------------
__device__ __half g_x16[(size_t)T_DIM * K_DIM];
__device__ __half g_w16[(size_t)N_DIM * K_DIM];
__device__ __half g_la16[(size_t)NGRP * R_DIM * K_DIM];
__device__ __half g_lb16[(size_t)NGRP * N_DIM * R_DIM];   // [g][n][r] transposed
__device__ __half g_sh16[(size_t)T_DIM * R_DIM];

// ---------------- asm helpers (base ISA only: sm_80-class) ------------------
__device__ __forceinline__ uint32_t smem_u32(const void* p) {
    uint32_t a;
    asm("{ .reg .u64 t; cvta.to.shared.u64 t, %1; cvt.u32.u64 %0, t; }"
        : "=r"(a) : "l"(p));
    return a;
}
#define CP16(dst, src) \
    asm volatile("cp.async.cg.shared.global [%0], [%1], 16;" :: "r"(dst), "l"(src))
#define CP_COMMIT() asm volatile("cp.async.commit_group;" ::: "memory")
#define CP_WAIT1()  asm volatile("cp.async.wait_group 1;"  ::: "memory")
#define CP_WAIT2()  asm volatile("cp.async.wait_group 2;"  ::: "memory")

#define LDSM4(d, addr) \
    asm volatile("ldmatrix.sync.aligned.m8n8.x4.shared.b16 {%0,%1,%2,%3}, [%4];" \
        : "=r"((d)[0]), "=r"((d)[1]), "=r"((d)[2]), "=r"((d)[3]) : "r"(addr))

#define MMA_F16(ac, a, b0, b1) \
    asm volatile("mma.sync.aligned.m16n8k16.row.col.f32.f16.f16.f32 " \
        "{%0,%1,%2,%3}, {%4,%5,%6,%7}, {%8,%9}, {%0,%1,%2,%3};" \
        : "+f"((ac)[0]), "+f"((ac)[1]), "+f"((ac)[2]), "+f"((ac)[3]) \
        : "r"((a)[0]), "r"((a)[1]), "r"((a)[2]), "r"((a)[3]), "r"(b0), "r"(b1))

// smem byte offset of 16B chunk (row, ch) within a tile of 128B rows (BK=64).
// Full 8-way XOR swizzle: ldmatrix (8 rows, same ch) hits 8 distinct 16B banks.
__device__ __forceinline__ uint32_t swz(int row, int ch) {
    return (uint32_t)((row << 7) | (((ch ^ (row & 7)) & 7) << 4));
}

__device__ __forceinline__ int find_group(const int* __restrict__ gl,
                                          int n_groups, int token) {
    int g = 0;
    while (g < n_groups - 1 && token >= gl[g]) g++;
    return g;
}

// ---------------- pre-pass kernels ------------------------------------------
#define NX4 ((size_t)T_DIM * K_DIM / 4)
#define NW4 ((size_t)N_DIM * K_DIM / 4)
#define NL4 ((size_t)NGRP * R_DIM * K_DIM / 4)

__global__ __launch_bounds__(256) void cvt_all_kernel(
    const float* __restrict__ x, const float* __restrict__ W,
    const float* __restrict__ la)
{
    size_t i = (size_t)blockIdx.x * 256 + threadIdx.x;
    const float* src;
    __half2* dst;
    size_t j;
    if (i < NX4) {
        src = x; dst = reinterpret_cast<__half2*>(g_x16); j = i;
    } else if (i < NX4 + NW4) {
        src = W; dst = reinterpret_cast<__half2*>(g_w16); j = i - NX4;
    } else {
        src = la; dst = reinterpret_cast<__half2*>(g_la16); j = i - NX4 - NW4;
    }
    float4 v = reinterpret_cast<const float4*>(src)[j];
    dst[2 * j]     = __floats2half2_rn(v.x, v.y);
    dst[2 * j + 1] = __floats2half2_rn(v.z, v.w);
}

// transpose lora_b[g][r][n] -> [g][n][r] fp16
__global__ __launch_bounds__(256) void lorab_t_kernel(const float* __restrict__ lb) {
    __shared__ float t[64][65];
    int g = blockIdx.y;
    int n0 = blockIdx.x * 64;
    for (int idx = threadIdx.x; idx < 4096; idx += 256) {
        int r = idx >> 6, n = idx & 63;
        t[n][r] = lb[((size_t)g * R_DIM + r) * N_DIM + n0 + n];
    }
    __syncthreads();
    for (int idx = threadIdx.x; idx < 4096; idx += 256) {
        int n = idx >> 6, r = idx & 63;
        g_lb16[((size_t)g * N_DIM + n0 + n) * R_DIM + r] = __float2half_rn(t[n][r]);
    }
}

// =============================================================================
// Shrink GEMM: shrink[8192,64] = x @ lora_a[g]^T, single fp16 term.
// CTA tile 128x64, 256 threads (8 warps: 4m x 2n, warp tile 32x32), BK=64.
// (unchanged)
// =============================================================================
#define SH_STAGE 24576
#define SH_CHUNKS (K_DIM / 64)   // 64

__global__ __launch_bounds__(256, 1) void shrink_gemm(
    const int* __restrict__ gl, int n_groups)
{
    extern __shared__ char smem[];
    uint32_t sb = smem_u32(smem);
    int tid = threadIdx.x, lane = tid & 31, w = tid >> 5;
    int m_off = (w & 3) * 32, n_off = (w >> 2) * 32;
    int row0 = blockIdx.x * 128;
    int g = find_group(gl, n_groups, row0);

    const __half* A = g_x16 + (size_t)row0 * K_DIM;
    const __half* B = g_la16 + (size_t)g * R_DIM * K_DIM;

    float acc[2][4][4];
    #pragma unroll
    for (int i = 0; i < 2; i++)
        #pragma unroll
        for (int j = 0; j < 4; j++)
            #pragma unroll
            for (int q = 0; q < 4; q++) acc[i][j][q] = 0.f;

    auto fill = [&](int s, int c) {
        uint32_t st = sb + s * SH_STAGE;
        #pragma unroll
        for (int it = 0; it < 6; it++) {
            int idx = tid + it * 256;
            if (idx < 1024) {
                int row = idx >> 3, ch = idx & 7;
                CP16(st + swz(row, ch),
                     A + (size_t)row * K_DIM + c * 64 + ch * 8);
            } else {
                int u = idx - 1024;
                int row = u >> 3, ch = u & 7;
                CP16(st + 16384 + swz(row, ch),
                     B + (size_t)row * K_DIM + c * 64 + ch * 8);
            }
        }
    };

    fill(0, 0); CP_COMMIT();
    fill(1, 1); CP_COMMIT();
    fill(2, 2); CP_COMMIT();

    for (int c = 0; c < SH_CHUNKS; c++) {
        CP_WAIT2();
        __syncthreads();
        uint32_t st = sb + (c & 3) * SH_STAGE;
        #pragma unroll
        for (int ks = 0; ks < 4; ks++) {
            uint32_t aa[2][4], bb[2][4];
            #pragma unroll
            for (int mt = 0; mt < 2; mt++) {
                int row = m_off + mt * 16 + (lane & 15);
                int ch = ks * 2 + (lane >> 4);
                LDSM4(aa[mt], st + swz(row, ch));
            }
            #pragma unroll
            for (int p = 0; p < 2; p++) {
                int row = n_off + p * 16 + (lane & 15);
                int ch = ks * 2 + (lane >> 4);
                LDSM4(bb[p], st + 16384 + swz(row, ch));
            }
            #pragma unroll
            for (int mt = 0; mt < 2; mt++)
                #pragma unroll
                for (int p = 0; p < 2; p++) {
                    MMA_F16(acc[mt][2 * p],     aa[mt], bb[p][0], bb[p][2]);
                    MMA_F16(acc[mt][2 * p + 1], aa[mt], bb[p][1], bb[p][3]);
                }
        }
        if (c + 3 < SH_CHUNKS) fill((c + 3) & 3, c + 3);
        CP_COMMIT();
    }

    #pragma unroll
    for (int mt = 0; mt < 2; mt++)
        #pragma unroll
        for (int j = 0; j < 4; j++) {
            int row = row0 + m_off + mt * 16 + (lane >> 2);
            int col = n_off + j * 8 + ((lane & 3) << 1);
            *reinterpret_cast<__half2*>(g_sh16 + (size_t)row * R_DIM + col)
                = __floats2half2_rn(acc[mt][j][0], acc[mt][j][1]);
            *reinterpret_cast<__half2*>(g_sh16 + (size_t)(row + 8) * R_DIM + col)
                = __floats2half2_rn(acc[mt][j][2], acc[mt][j][3]);
        }
}

// =============================================================================
// Main GEMM: out[8192,4096] = x @ W^T (+ fused LoRA expand over rank 64).
// R12: exact R10 pipeline (XOR swz, 3 x 32KB stages, fill-after-compute,
// 2 CTAs/SM) but 128 threads / 4 warps of 64x64 (2m x 2n). Cuts LDSM traffic
// 33% below the HMMA floor; cross-CTA desync covers the 2-warps/SMSP latency.
// =============================================================================
#define MN_STAGE 32768
#define MN_CHUNKS (K_DIM / 64 + 1)   // 65

__global__ __launch_bounds__(128, 2) void gemm_main(
    const int* __restrict__ gl, int n_groups, float* __restrict__ out)
{
    extern __shared__ char smem[];
    uint32_t sb = smem_u32(smem);
    int tid = threadIdx.x, lane = tid & 31, w = tid >> 5;
    int m_off = (w & 1) * 64, n_off = (w >> 1) * 64;
    int row0 = blockIdx.y * 128;
    int col0 = blockIdx.x * 128;
    int g = find_group(gl, n_groups, row0);

    // acc[mt][j][4]: mt = m16 block (4), j = n8 block (8) -> 64x64 warp tile
    float acc[4][8][4];
    #pragma unroll
    for (int i = 0; i < 4; i++)
        #pragma unroll
        for (int j = 0; j < 8; j++)
            #pragma unroll
            for (int q = 0; q < 4; q++) acc[i][j][q] = 0.f;

    auto fill = [&](int s, int c) {
        uint32_t st = sb + s * MN_STAGE;
        const __half *pA, *pB;
        size_t lda, ldb;
        if (c < K_DIM / 64) {
            pA = g_x16 + (size_t)row0 * K_DIM + c * 64;
            pB = g_w16 + (size_t)col0 * K_DIM + c * 64;
            lda = K_DIM; ldb = K_DIM;
        } else {
            pA = g_sh16 + (size_t)row0 * R_DIM;
            pB = g_lb16 + ((size_t)g * N_DIM + col0) * R_DIM;
            lda = R_DIM; ldb = R_DIM;
        }
        #pragma unroll
        for (int it = 0; it < 16; it++) {
            int idx = tid + it * 128;
            if (idx < 1024) {               // A: 128 rows x 8 ch
                int row = idx >> 3, ch = idx & 7;
                CP16(st + swz(row, ch), pA + (size_t)row * lda + ch * 8);
            } else {                        // B: 128 rows x 8 ch
                int u = idx - 1024;
                int row = u >> 3, ch = u & 7;
                CP16(st + 16384 + swz(row, ch), pB + (size_t)row * ldb + ch * 8);
            }
        }
    };

    fill(0, 0); CP_COMMIT();
    fill(1, 1); CP_COMMIT();

    for (int c = 0; c < MN_CHUNKS; c++) {
        CP_WAIT1();
        __syncthreads();
        uint32_t st = sb + (c % 3) * MN_STAGE;
        #pragma unroll
        for (int ks = 0; ks < 4; ks++) {
            uint32_t aa[4][4];
            #pragma unroll
            for (int mt = 0; mt < 4; mt++) {
                int row = m_off + mt * 16 + (lane & 15);
                int ch = ks * 2 + (lane >> 4);
                LDSM4(aa[mt], st + swz(row, ch));
            }
            #pragma unroll
            for (int p = 0; p < 4; p++) {
                uint32_t bb[4];
                int row = n_off + p * 16 + (lane & 15);
                int ch = ks * 2 + (lane >> 4);
                LDSM4(bb, st + 16384 + swz(row, ch));
                #pragma unroll
                for (int mt = 0; mt < 4; mt++) {
                    MMA_F16(acc[mt][2 * p],     aa[mt], bb[0], bb[2]);
                    MMA_F16(acc[mt][2 * p + 1], aa[mt], bb[1], bb[3]);
                }
            }
        }
        if (c + 2 < MN_CHUNKS) fill((c + 2) % 3, c + 2);
        CP_COMMIT();
    }

    #pragma unroll
    for (int mt = 0; mt < 4; mt++)
        #pragma unroll
        for (int j = 0; j < 8; j++) {
            int row = row0 + m_off + mt * 16 + (lane >> 2);
            int col = col0 + n_off + j * 8 + ((lane & 3) << 1);
            *reinterpret_cast<float2*>(out + (size_t)row * N_DIM + col)
                = make_float2(acc[mt][j][0], acc[mt][j][1]);
            *reinterpret_cast<float2*>(out + (size_t)(row + 8) * N_DIM + col)
                = make_float2(acc[mt][j][2], acc[mt][j][3]);
        }
}

// ---------------- launch -----------------------------------------------------
extern "C" void kernel_launch(void* const* d_in, const int* in_sizes, int n_in,
                              void* d_out, int out_size) {
    const float* x      = (const float*)d_in[0];
    const float* W      = (const float*)d_in[1];
    const float* lora_a = (const float*)d_in[2];
    const float* lora_b = (const float*)d_in[3];
    const int*   gl     = (const int*)d_in[4];
    const int n_groups  = in_sizes[4];
    float* out = (float*)d_out;

    cudaFuncSetAttribute(shrink_gemm, cudaFuncAttributeMaxDynamicSharedMemorySize,
                         4 * SH_STAGE);
    cudaFuncSetAttribute(gemm_main, cudaFuncAttributeMaxDynamicSharedMemorySize,
                         3 * MN_STAGE);

    // launch order: cvt_all(0), lorab(1), shrink(2), gemm_main(3)
    cvt_all_kernel<<<(unsigned)((NX4 + NW4 + NL4) / 256), 256>>>(x, W, lora_a);
    lorab_t_kernel<<<dim3(N_DIM / 64, NGRP), 256>>>(lora_b);
    shrink_gemm<<<T_DIM / 128, 256, 4 * SH_STAGE>>>(gl, n_groups);
    gemm_main<<<dim3(N_DIM / 128, T_DIM / 128), 128, 3 * MN_STAGE>>>(
        gl, n_groups, out);
}

// round 13
// speedup vs baseline: 1.1862x; 1.1542x over previous
#include <cuda_runtime.h>
#include <cuda_fp16.h>
#include <cstdint>

#define T_DIM 8192
#define K_DIM 4096
#define N_DIM 4096
#define R_DIM 64
#define NGRP  8

// ---------------- static device scratch (alloc forbidden) -------------------
__device__ __half g_x16[(size_t)T_DIM * K_DIM];
__device__ __half g_w16[(size_t)N_DIM * K_DIM];
__device__ __half g_la16[(size_t)NGRP * R_DIM * K_DIM];
__device__ __half g_lb16[(size_t)NGRP * N_DIM * R_DIM];   // [g][n][r] transposed
__device__ __half g_sh16[(size_t)T_DIM * R_DIM];

// ---------------- asm helpers (base ISA only: sm_80-class) ------------------
__device__ __forceinline__ uint32_t smem_u32(const void* p) {
    uint32_t a;
    asm("{ .reg .u64 t; cvta.to.shared.u64 t, %1; cvt.u32.u64 %0, t; }"
        : "=r"(a) : "l"(p));
    return a;
}
#define CP16(dst, src) \
    asm volatile("cp.async.cg.shared.global [%0], [%1], 16;" :: "r"(dst), "l"(src))
#define CP_COMMIT() asm volatile("cp.async.commit_group;" ::: "memory")
#define CP_WAIT1()  asm volatile("cp.async.wait_group 1;"  ::: "memory")
#define CP_WAIT2()  asm volatile("cp.async.wait_group 2;"  ::: "memory")

#define LDSM4(d, addr) \
    asm volatile("ldmatrix.sync.aligned.m8n8.x4.shared.b16 {%0,%1,%2,%3}, [%4];" \
        : "=r"((d)[0]), "=r"((d)[1]), "=r"((d)[2]), "=r"((d)[3]) : "r"(addr))

#define MMA_F16(ac, a, b0, b1) \
    asm volatile("mma.sync.aligned.m16n8k16.row.col.f32.f16.f16.f32 " \
        "{%0,%1,%2,%3}, {%4,%5,%6,%7}, {%8,%9}, {%0,%1,%2,%3};" \
        : "+f"((ac)[0]), "+f"((ac)[1]), "+f"((ac)[2]), "+f"((ac)[3]) \
        : "r"((a)[0]), "r"((a)[1]), "r"((a)[2]), "r"((a)[3]), "r"(b0), "r"(b1))

// smem byte offset of 16B chunk (row, ch) within a tile of 128B rows (BK=64).
// Full 8-way XOR swizzle: ldmatrix (8 rows, same ch) hits 8 distinct 16B banks.
__device__ __forceinline__ uint32_t swz(int row, int ch) {
    return (uint32_t)((row << 7) | (((ch ^ (row & 7)) & 7) << 4));
}

__device__ __forceinline__ int find_group(const int* __restrict__ gl,
                                          int n_groups, int token) {
    int g = 0;
    while (g < n_groups - 1 && token >= gl[g]) g++;
    return g;
}

// ---------------- fused pre-pass: cvt(x,W,la) + lorab transpose -------------
#define NX4 ((size_t)T_DIM * K_DIM / 4)
#define NW4 ((size_t)N_DIM * K_DIM / 4)
#define NL4 ((size_t)NGRP * R_DIM * K_DIM / 4)
#define CVT_BLK ((unsigned)((NX4 + NW4 + NL4) / 256))

__global__ __launch_bounds__(256) void pre_kernel(
    const float* __restrict__ x, const float* __restrict__ W,
    const float* __restrict__ la, const float* __restrict__ lb)
{
    if (blockIdx.x < CVT_BLK) {
        size_t i = (size_t)blockIdx.x * 256 + threadIdx.x;
        const float* src;
        __half2* dst;
        size_t j;
        if (i < NX4) {
            src = x; dst = reinterpret_cast<__half2*>(g_x16); j = i;
        } else if (i < NX4 + NW4) {
            src = W; dst = reinterpret_cast<__half2*>(g_w16); j = i - NX4;
        } else {
            src = la; dst = reinterpret_cast<__half2*>(g_la16); j = i - NX4 - NW4;
        }
        float4 v = reinterpret_cast<const float4*>(src)[j];
        dst[2 * j]     = __floats2half2_rn(v.x, v.y);
        dst[2 * j + 1] = __floats2half2_rn(v.z, v.w);
    } else {
        // lorab transpose: [g][r][n] -> [g][n][r]
        __shared__ float t[64][65];
        int b = blockIdx.x - CVT_BLK;        // 0..511
        int g = b >> 6;
        int n0 = (b & 63) * 64;
        for (int idx = threadIdx.x; idx < 4096; idx += 256) {
            int r = idx >> 6, n = idx & 63;
            t[n][r] = lb[((size_t)g * R_DIM + r) * N_DIM + n0 + n];
        }
        __syncthreads();
        for (int idx = threadIdx.x; idx < 4096; idx += 256) {
            int n = idx >> 6, r = idx & 63;
            g_lb16[((size_t)g * N_DIM + n0 + n) * R_DIM + r] =
                __float2half_rn(t[n][r]);
        }
    }
}

// =============================================================================
// Shrink GEMM: shrink[8192,64] = x @ lora_a[g]^T, single fp16 term.
// CTA tile 128x64, 256 threads (8 warps: 4m x 2n, warp tile 32x32), BK=64.
// (unchanged — ~40us)
// =============================================================================
#define SH_STAGE 24576
#define SH_CHUNKS (K_DIM / 64)   // 64

__global__ __launch_bounds__(256, 1) void shrink_gemm(
    const int* __restrict__ gl, int n_groups)
{
    extern __shared__ char smem[];
    uint32_t sb = smem_u32(smem);
    int tid = threadIdx.x, lane = tid & 31, w = tid >> 5;
    int m_off = (w & 3) * 32, n_off = (w >> 2) * 32;
    int row0 = blockIdx.x * 128;
    int g = find_group(gl, n_groups, row0);

    const __half* A = g_x16 + (size_t)row0 * K_DIM;
    const __half* B = g_la16 + (size_t)g * R_DIM * K_DIM;

    float acc[2][4][4];
    #pragma unroll
    for (int i = 0; i < 2; i++)
        #pragma unroll
        for (int j = 0; j < 4; j++)
            #pragma unroll
            for (int q = 0; q < 4; q++) acc[i][j][q] = 0.f;

    auto fill = [&](int s, int c) {
        uint32_t st = sb + s * SH_STAGE;
        #pragma unroll
        for (int it = 0; it < 6; it++) {
            int idx = tid + it * 256;
            if (idx < 1024) {
                int row = idx >> 3, ch = idx & 7;
                CP16(st + swz(row, ch),
                     A + (size_t)row * K_DIM + c * 64 + ch * 8);
            } else {
                int u = idx - 1024;
                int row = u >> 3, ch = u & 7;
                CP16(st + 16384 + swz(row, ch),
                     B + (size_t)row * K_DIM + c * 64 + ch * 8);
            }
        }
    };

    fill(0, 0); CP_COMMIT();
    fill(1, 1); CP_COMMIT();
    fill(2, 2); CP_COMMIT();

    for (int c = 0; c < SH_CHUNKS; c++) {
        CP_WAIT2();
        __syncthreads();
        uint32_t st = sb + (c & 3) * SH_STAGE;
        #pragma unroll
        for (int ks = 0; ks < 4; ks++) {
            uint32_t aa[2][4], bb[2][4];
            #pragma unroll
            for (int mt = 0; mt < 2; mt++) {
                int row = m_off + mt * 16 + (lane & 15);
                int ch = ks * 2 + (lane >> 4);
                LDSM4(aa[mt], st + swz(row, ch));
            }
            #pragma unroll
            for (int p = 0; p < 2; p++) {
                int row = n_off + p * 16 + (lane & 15);
                int ch = ks * 2 + (lane >> 4);
                LDSM4(bb[p], st + 16384 + swz(row, ch));
            }
            #pragma unroll
            for (int mt = 0; mt < 2; mt++)
                #pragma unroll
                for (int p = 0; p < 2; p++) {
                    MMA_F16(acc[mt][2 * p],     aa[mt], bb[p][0], bb[p][2]);
                    MMA_F16(acc[mt][2 * p + 1], aa[mt], bb[p][1], bb[p][3]);
                }
        }
        if (c + 3 < SH_CHUNKS) fill((c + 3) & 3, c + 3);
        CP_COMMIT();
    }

    #pragma unroll
    for (int mt = 0; mt < 2; mt++)
        #pragma unroll
        for (int j = 0; j < 4; j++) {
            int row = row0 + m_off + mt * 16 + (lane >> 2);
            int col = n_off + j * 8 + ((lane & 3) << 1);
            *reinterpret_cast<__half2*>(g_sh16 + (size_t)row * R_DIM + col)
                = __floats2half2_rn(acc[mt][j][0], acc[mt][j][1]);
            *reinterpret_cast<__half2*>(g_sh16 + (size_t)(row + 8) * R_DIM + col)
                = __floats2half2_rn(acc[mt][j][2], acc[mt][j][3]);
        }
}

// =============================================================================
// Main GEMM: out[8192,4096] = x @ W^T (+ fused LoRA expand over rank 64).
// R13 = R10 (CTA 128x128, 256 thr, 8 warps 4m x 2n of 32x64, BK=64, 3 x 32KB
// stages, 2 CTAs/SM, fill-after-compute) with ALL address math hoisted:
//   swz(row, ks*2+par) = const_per_target + k_off[ks]
//   (row low-3 bits == lane&7 for every LDSM target -> shared k_off table)
// and fill global pointers advancing +64 halves/chunk (LoRA chunk peeled).
// =============================================================================
#define MN_STAGE 32768
#define MN_BASEC (K_DIM / 64)        // 64 base chunks
#define MN_CHUNKS (MN_BASEC + 1)     // + 1 LoRA chunk

__global__ __launch_bounds__(256, 2) void gemm_main(
    const int* __restrict__ gl, int n_groups, float* __restrict__ out)
{
    extern __shared__ char smem[];
    uint32_t sb = smem_u32(smem);
    int tid = threadIdx.x, lane = tid & 31, w = tid >> 5;
    int m_off = (w & 3) * 32, n_off = (w >> 2) * 64;
    int row0 = blockIdx.y * 128;
    int col0 = blockIdx.x * 128;
    int g = find_group(gl, n_groups, row0);

    float acc[2][8][4];
    #pragma unroll
    for (int i = 0; i < 2; i++)
        #pragma unroll
        for (int j = 0; j < 8; j++)
            #pragma unroll
            for (int q = 0; q < 4; q++) acc[i][j][q] = 0.f;

    // ---- hoisted LDSM addressing ----
    const int lr  = lane & 15;
    const int par = lane >> 4;
    const int r   = lr & 7;                       // row&7, same for all targets
    const uint32_t pbit = (uint32_t)((par ^ (r & 1)) << 4);
    const int rk = (r >> 1) & 3;
    uint32_t k_off[4];
    #pragma unroll
    for (int ks = 0; ks < 4; ks++) k_off[ks] = (uint32_t)(((ks ^ rk) & 3) << 5);
    uint32_t a_cst[2], b_cst[4];
    #pragma unroll
    for (int mt = 0; mt < 2; mt++)
        a_cst[mt] = (uint32_t)((m_off + mt * 16 + lr) << 7) + pbit;
    #pragma unroll
    for (int p = 0; p < 4; p++)
        b_cst[p] = 16384u + (uint32_t)((n_off + p * 16 + lr) << 7) + pbit;

    // ---- hoisted fill addressing (8 CP16s/thread: 4 A + 4 B) ----
    uint32_t s_off[8];
    int      g_off[8];
    #pragma unroll
    for (int it = 0; it < 8; it++) {
        int idx = tid + it * 256;
        if (idx < 1024) {                   // A: 128 rows x 8 ch
            int row = idx >> 3, ch = idx & 7;
            s_off[it] = swz(row, ch);
            g_off[it] = row * K_DIM + ch * 8;
        } else {                            // B: 128 rows x 8 ch
            int u = idx - 1024;
            int row = u >> 3, ch = u & 7;
            s_off[it] = 16384u + swz(row, ch);
            g_off[it] = row * K_DIM + ch * 8;
        }
    }
    const __half* pAf = g_x16 + (size_t)row0 * K_DIM;   // advances +64/chunk
    const __half* pBf = g_w16 + (size_t)col0 * K_DIM;

    auto fill_main = [&](uint32_t st) {
        #pragma unroll
        for (int it = 0; it < 4; it++)
            CP16(st + s_off[it], pAf + g_off[it]);
        #pragma unroll
        for (int it = 4; it < 8; it++)
            CP16(st + s_off[it], pBf + g_off[it]);
        pAf += 64; pBf += 64;
    };
    auto fill_lora = [&](uint32_t st) {
        const __half* pA = g_sh16 + (size_t)row0 * R_DIM;
        const __half* pB = g_lb16 + ((size_t)g * N_DIM + col0) * R_DIM;
        #pragma unroll
        for (int it = 0; it < 8; it++) {
            int idx = tid + it * 256;
            if (idx < 1024) {
                int row = idx >> 3, ch = idx & 7;
                CP16(st + swz(row, ch), pA + row * R_DIM + ch * 8);
            } else {
                int u = idx - 1024;
                int row = u >> 3, ch = u & 7;
                CP16(st + 16384u + swz(row, ch), pB + row * R_DIM + ch * 8);
            }
        }
    };

    fill_main(sb);             CP_COMMIT();
    fill_main(sb + MN_STAGE);  CP_COMMIT();

    uint32_t st_c = sb;                       // compute stage
    uint32_t st_f = sb + 2u * MN_STAGE;       // fill stage (== (c+2)%3)
    const uint32_t st_top = sb + 2u * MN_STAGE;

    for (int c = 0; c < MN_CHUNKS; c++) {
        CP_WAIT1();
        __syncthreads();
        #pragma unroll
        for (int ks = 0; ks < 4; ks++) {
            uint32_t aa[2][4], bb[4][4];
            #pragma unroll
            for (int mt = 0; mt < 2; mt++)
                LDSM4(aa[mt], st_c + a_cst[mt] + k_off[ks]);
            #pragma unroll
            for (int p = 0; p < 4; p++)
                LDSM4(bb[p], st_c + b_cst[p] + k_off[ks]);
            #pragma unroll
            for (int mt = 0; mt < 2; mt++)
                #pragma unroll
                for (int p = 0; p < 4; p++) {
                    MMA_F16(acc[mt][2 * p],     aa[mt], bb[p][0], bb[p][2]);
                    MMA_F16(acc[mt][2 * p + 1], aa[mt], bb[p][1], bb[p][3]);
                }
        }
        if (c + 2 < MN_BASEC)       fill_main(st_f);
        else if (c + 2 == MN_BASEC) fill_lora(st_f);
        CP_COMMIT();
        st_c = (st_c == st_top) ? sb : st_c + MN_STAGE;
        st_f = (st_f == st_top) ? sb : st_f + MN_STAGE;
    }

    #pragma unroll
    for (int mt = 0; mt < 2; mt++)
        #pragma unroll
        for (int j = 0; j < 8; j++) {
            int row = row0 + m_off + mt * 16 + (lane >> 2);
            int col = col0 + n_off + j * 8 + ((lane & 3) << 1);
            *reinterpret_cast<float2*>(out + (size_t)row * N_DIM + col)
                = make_float2(acc[mt][j][0], acc[mt][j][1]);
            *reinterpret_cast<float2*>(out + (size_t)(row + 8) * N_DIM + col)
                = make_float2(acc[mt][j][2], acc[mt][j][3]);
        }
}

// ---------------- launch -----------------------------------------------------
extern "C" void kernel_launch(void* const* d_in, const int* in_sizes, int n_in,
                              void* d_out, int out_size) {
    const float* x      = (const float*)d_in[0];
    const float* W      = (const float*)d_in[1];
    const float* lora_a = (const float*)d_in[2];
    const float* lora_b = (const float*)d_in[3];
    const int*   gl     = (const int*)d_in[4];
    const int n_groups  = in_sizes[4];
    float* out = (float*)d_out;

    cudaFuncSetAttribute(shrink_gemm, cudaFuncAttributeMaxDynamicSharedMemorySize,
                         4 * SH_STAGE);
    cudaFuncSetAttribute(gemm_main, cudaFuncAttributeMaxDynamicSharedMemorySize,
                         3 * MN_STAGE);

    pre_kernel<<<CVT_BLK + 512, 256>>>(x, W, lora_a, lora_b);
    shrink_gemm<<<T_DIM / 128, 256, 4 * SH_STAGE>>>(gl, n_groups);
    gemm_main<<<dim3(N_DIM / 128, T_DIM / 128), 256, 3 * MN_STAGE>>>(
        gl, n_groups, out);
}

// round 14
// speedup vs baseline: 1.2414x; 1.0466x over previous
#include <cuda_runtime.h>
#include <cuda_fp16.h>
#include <cstdint>

#define T_DIM 8192
#define K_DIM 4096
#define N_DIM 4096
#define R_DIM 64
#define NGRP  8

// ---------------- static device scratch (alloc forbidden) -------------------
__device__ __half g_x16[(size_t)T_DIM * K_DIM];
__device__ __half g_w16[(size_t)N_DIM * K_DIM];
__device__ __half g_la16[(size_t)NGRP * R_DIM * K_DIM];
__device__ __half g_lb16[(size_t)NGRP * N_DIM * R_DIM];   // [g][n][r] transposed
__device__ __half g_sh16[(size_t)T_DIM * R_DIM];
__device__ int    g_flag;   // shrink-done counter (reset by pre_kernel)

// ---------------- asm helpers (base ISA only: sm_80-class) ------------------
__device__ __forceinline__ uint32_t smem_u32(const void* p) {
    uint32_t a;
    asm("{ .reg .u64 t; cvta.to.shared.u64 t, %1; cvt.u32.u64 %0, t; }"
        : "=r"(a) : "l"(p));
    return a;
}
#define CP16(dst, src) \
    asm volatile("cp.async.cg.shared.global [%0], [%1], 16;" :: "r"(dst), "l"(src))
#define CP_COMMIT() asm volatile("cp.async.commit_group;" ::: "memory")
#define CP_WAIT1()  asm volatile("cp.async.wait_group 1;"  ::: "memory")
#define CP_WAIT2()  asm volatile("cp.async.wait_group 2;"  ::: "memory")

#define LDSM4(d, addr) \
    asm volatile("ldmatrix.sync.aligned.m8n8.x4.shared.b16 {%0,%1,%2,%3}, [%4];" \
        : "=r"((d)[0]), "=r"((d)[1]), "=r"((d)[2]), "=r"((d)[3]) : "r"(addr))

#define MMA_F16(ac, a, b0, b1) \
    asm volatile("mma.sync.aligned.m16n8k16.row.col.f32.f16.f16.f32 " \
        "{%0,%1,%2,%3}, {%4,%5,%6,%7}, {%8,%9}, {%0,%1,%2,%3};" \
        : "+f"((ac)[0]), "+f"((ac)[1]), "+f"((ac)[2]), "+f"((ac)[3]) \
        : "r"((a)[0]), "r"((a)[1]), "r"((a)[2]), "r"((a)[3]), "r"(b0), "r"(b1))

// smem byte offset of 16B chunk (row, ch) within a tile of 128B rows (BK=64).
__device__ __forceinline__ uint32_t swz(int row, int ch) {
    return (uint32_t)((row << 7) | (((ch ^ (row & 7)) & 7) << 4));
}

__device__ __forceinline__ int find_group(const int* __restrict__ gl,
                                          int n_groups, int token) {
    int g = 0;
    while (g < n_groups - 1 && token >= gl[g]) g++;
    return g;
}

// ---------------- fused pre-pass: cvt(x,W,la) + lorab transpose -------------
#define NX4 ((size_t)T_DIM * K_DIM / 4)
#define NW4 ((size_t)N_DIM * K_DIM / 4)
#define NL4 ((size_t)NGRP * R_DIM * K_DIM / 4)
#define CVT_BLK ((unsigned)((NX4 + NW4 + NL4) / 256))

__global__ __launch_bounds__(256) void pre_kernel(
    const float* __restrict__ x, const float* __restrict__ W,
    const float* __restrict__ la, const float* __restrict__ lb)
{
    if (blockIdx.x == 0 && threadIdx.x == 0) g_flag = 0;
    if (blockIdx.x < CVT_BLK) {
        size_t i = (size_t)blockIdx.x * 256 + threadIdx.x;
        const float* src;
        __half2* dst;
        size_t j;
        if (i < NX4) {
            src = x; dst = reinterpret_cast<__half2*>(g_x16); j = i;
        } else if (i < NX4 + NW4) {
            src = W; dst = reinterpret_cast<__half2*>(g_w16); j = i - NX4;
        } else {
            src = la; dst = reinterpret_cast<__half2*>(g_la16); j = i - NX4 - NW4;
        }
        float4 v = reinterpret_cast<const float4*>(src)[j];
        dst[2 * j]     = __floats2half2_rn(v.x, v.y);
        dst[2 * j + 1] = __floats2half2_rn(v.z, v.w);
    } else {
        // lorab transpose: [g][r][n] -> [g][n][r]
        __shared__ float t[64][65];
        int b = blockIdx.x - CVT_BLK;        // 0..511
        int g = b >> 6;
        int n0 = (b & 63) * 64;
        for (int idx = threadIdx.x; idx < 4096; idx += 256) {
            int r = idx >> 6, n = idx & 63;
            t[n][r] = lb[((size_t)g * R_DIM + r) * N_DIM + n0 + n];
        }
        __syncthreads();
        for (int idx = threadIdx.x; idx < 4096; idx += 256) {
            int n = idx >> 6, r = idx & 63;
            g_lb16[((size_t)g * N_DIM + n0 + n) * R_DIM + r] =
                __float2half_rn(t[n][r]);
        }
    }
}

// =============================================================================
// Fused main kernel.
// Blocks 0..63:   shrink tile (CTA 128x64, 4 x 24KB stages = 96KB smem).
//                 First 64 linear block indices -> guaranteed wave-1 residency;
//                 depend on nothing -> no deadlock. Release via threadfence +
//                 atomicAdd(g_flag).
// Blocks 64..2111: GEMM tile (R13 config: CTA 128x128, 8 warps 4m x 2n of
//                 32x64, BK=64, 3 x 32KB stages = 96KB, 2 CTAs/SM, hoisted
//                 swizzle addressing). Acquire spin on g_flag at c==62, right
//                 before the LoRA chunk fill — ~240us after shrink finishes.
// =============================================================================
#define SH_STAGE 24576
#define SH_CHUNKS (K_DIM / 64)       // 64
#define MN_STAGE 32768
#define MN_BASEC (K_DIM / 64)        // 64 base chunks
#define MN_CHUNKS (MN_BASEC + 1)     // + 1 LoRA chunk
#define SMEM_BYTES 98304             // == 4*SH_STAGE == 3*MN_STAGE

__global__ __launch_bounds__(256, 2) void fused_main(
    const int* __restrict__ gl, int n_groups, float* __restrict__ out)
{
    extern __shared__ char smem[];
    uint32_t sb = smem_u32(smem);
    int tid = threadIdx.x, lane = tid & 31, w = tid >> 5;

    if (blockIdx.x < 64) {
        // ------------------------- shrink path ------------------------------
        int m_off = (w & 3) * 32, n_off = (w >> 2) * 32;
        int row0 = blockIdx.x * 128;
        int g = find_group(gl, n_groups, row0);

        const __half* A = g_x16 + (size_t)row0 * K_DIM;
        const __half* B = g_la16 + (size_t)g * R_DIM * K_DIM;

        float acc[2][4][4];
        #pragma unroll
        for (int i = 0; i < 2; i++)
            #pragma unroll
            for (int j = 0; j < 4; j++)
                #pragma unroll
                for (int q = 0; q < 4; q++) acc[i][j][q] = 0.f;

        auto fill = [&](int s, int c) {
            uint32_t st = sb + s * SH_STAGE;
            #pragma unroll
            for (int it = 0; it < 6; it++) {
                int idx = tid + it * 256;
                if (idx < 1024) {
                    int row = idx >> 3, ch = idx & 7;
                    CP16(st + swz(row, ch),
                         A + (size_t)row * K_DIM + c * 64 + ch * 8);
                } else {
                    int u = idx - 1024;
                    int row = u >> 3, ch = u & 7;
                    CP16(st + 16384 + swz(row, ch),
                         B + (size_t)row * K_DIM + c * 64 + ch * 8);
                }
            }
        };

        fill(0, 0); CP_COMMIT();
        fill(1, 1); CP_COMMIT();
        fill(2, 2); CP_COMMIT();

        for (int c = 0; c < SH_CHUNKS; c++) {
            CP_WAIT2();
            __syncthreads();
            uint32_t st = sb + (c & 3) * SH_STAGE;
            #pragma unroll
            for (int ks = 0; ks < 4; ks++) {
                uint32_t aa[2][4], bb[2][4];
                #pragma unroll
                for (int mt = 0; mt < 2; mt++) {
                    int row = m_off + mt * 16 + (lane & 15);
                    int ch = ks * 2 + (lane >> 4);
                    LDSM4(aa[mt], st + swz(row, ch));
                }
                #pragma unroll
                for (int p = 0; p < 2; p++) {
                    int row = n_off + p * 16 + (lane & 15);
                    int ch = ks * 2 + (lane >> 4);
                    LDSM4(bb[p], st + 16384 + swz(row, ch));
                }
                #pragma unroll
                for (int mt = 0; mt < 2; mt++)
                    #pragma unroll
                    for (int p = 0; p < 2; p++) {
                        MMA_F16(acc[mt][2 * p],     aa[mt], bb[p][0], bb[p][2]);
                        MMA_F16(acc[mt][2 * p + 1], aa[mt], bb[p][1], bb[p][3]);
                    }
            }
            if (c + 3 < SH_CHUNKS) fill((c + 3) & 3, c + 3);
            CP_COMMIT();
        }

        #pragma unroll
        for (int mt = 0; mt < 2; mt++)
            #pragma unroll
            for (int j = 0; j < 4; j++) {
                int row = row0 + m_off + mt * 16 + (lane >> 2);
                int col = n_off + j * 8 + ((lane & 3) << 1);
                *reinterpret_cast<__half2*>(g_sh16 + (size_t)row * R_DIM + col)
                    = __floats2half2_rn(acc[mt][j][0], acc[mt][j][1]);
                *reinterpret_cast<__half2*>(g_sh16 + (size_t)(row + 8) * R_DIM + col)
                    = __floats2half2_rn(acc[mt][j][2], acc[mt][j][3]);
            }
        __syncthreads();
        __threadfence();                     // release g_sh16 writes
        if (tid == 0) atomicAdd(&g_flag, 1);
        return;
    }

    // ----------------------------- GEMM path --------------------------------
    int b = blockIdx.x - 64;
    int col0 = (b & 31) * 128;
    int row0 = (b >> 5) * 128;
    int m_off = (w & 3) * 32, n_off = (w >> 2) * 64;
    int g = find_group(gl, n_groups, row0);

    float acc[2][8][4];
    #pragma unroll
    for (int i = 0; i < 2; i++)
        #pragma unroll
        for (int j = 0; j < 8; j++)
            #pragma unroll
            for (int q = 0; q < 4; q++) acc[i][j][q] = 0.f;

    // ---- hoisted LDSM addressing ----
    const int lr  = lane & 15;
    const int par = lane >> 4;
    const int r   = lr & 7;
    const uint32_t pbit = (uint32_t)((par ^ (r & 1)) << 4);
    const int rk = (r >> 1) & 3;
    uint32_t k_off[4];
    #pragma unroll
    for (int ks = 0; ks < 4; ks++) k_off[ks] = (uint32_t)(((ks ^ rk) & 3) << 5);
    uint32_t a_cst[2], b_cst[4];
    #pragma unroll
    for (int mt = 0; mt < 2; mt++)
        a_cst[mt] = (uint32_t)((m_off + mt * 16 + lr) << 7) + pbit;
    #pragma unroll
    for (int p = 0; p < 4; p++)
        b_cst[p] = 16384u + (uint32_t)((n_off + p * 16 + lr) << 7) + pbit;

    // ---- hoisted fill addressing (8 CP16s/thread: 4 A + 4 B) ----
    uint32_t s_off[8];
    int      g_off[8];
    #pragma unroll
    for (int it = 0; it < 8; it++) {
        int idx = tid + it * 256;
        if (idx < 1024) {
            int row = idx >> 3, ch = idx & 7;
            s_off[it] = swz(row, ch);
            g_off[it] = row * K_DIM + ch * 8;
        } else {
            int u = idx - 1024;
            int row = u >> 3, ch = u & 7;
            s_off[it] = 16384u + swz(row, ch);
            g_off[it] = row * K_DIM + ch * 8;
        }
    }
    const __half* pAf = g_x16 + (size_t)row0 * K_DIM;
    const __half* pBf = g_w16 + (size_t)col0 * K_DIM;

    auto fill_main = [&](uint32_t st) {
        #pragma unroll
        for (int it = 0; it < 4; it++)
            CP16(st + s_off[it], pAf + g_off[it]);
        #pragma unroll
        for (int it = 4; it < 8; it++)
            CP16(st + s_off[it], pBf + g_off[it]);
        pAf += 64; pBf += 64;
    };
    auto fill_lora = [&](uint32_t st) {
        const __half* pA = g_sh16 + (size_t)row0 * R_DIM;
        const __half* pB = g_lb16 + ((size_t)g * N_DIM + col0) * R_DIM;
        #pragma unroll
        for (int it = 0; it < 8; it++) {
            int idx = tid + it * 256;
            if (idx < 1024) {
                int row = idx >> 3, ch = idx & 7;
                CP16(st + swz(row, ch), pA + row * R_DIM + ch * 8);
            } else {
                int u = idx - 1024;
                int row = u >> 3, ch = u & 7;
                CP16(st + 16384u + swz(row, ch), pB + row * R_DIM + ch * 8);
            }
        }
    };

    fill_main(sb);             CP_COMMIT();
    fill_main(sb + MN_STAGE);  CP_COMMIT();

    uint32_t st_c = sb;
    uint32_t st_f = sb + 2u * MN_STAGE;
    const uint32_t st_top = sb + 2u * MN_STAGE;

    for (int c = 0; c < MN_CHUNKS; c++) {
        CP_WAIT1();
        __syncthreads();
        #pragma unroll
        for (int ks = 0; ks < 4; ks++) {
            uint32_t aa[2][4], bb[4][4];
            #pragma unroll
            for (int mt = 0; mt < 2; mt++)
                LDSM4(aa[mt], st_c + a_cst[mt] + k_off[ks]);
            #pragma unroll
            for (int p = 0; p < 4; p++)
                LDSM4(bb[p], st_c + b_cst[p] + k_off[ks]);
            #pragma unroll
            for (int mt = 0; mt < 2; mt++)
                #pragma unroll
                for (int p = 0; p < 4; p++) {
                    MMA_F16(acc[mt][2 * p],     aa[mt], bb[p][0], bb[p][2]);
                    MMA_F16(acc[mt][2 * p + 1], aa[mt], bb[p][1], bb[p][3]);
                }
        }
        if (c + 2 < MN_BASEC) {
            fill_main(st_f);
        } else if (c + 2 == MN_BASEC) {
            // acquire: all 64 shrink blocks must have released g_sh16
            if (tid == 0) {
                while (atomicAdd(&g_flag, 0) < 64) { }
            }
            __syncthreads();
            __threadfence();
            fill_lora(st_f);
        }
        CP_COMMIT();
        st_c = (st_c == st_top) ? sb : st_c + MN_STAGE;
        st_f = (st_f == st_top) ? sb : st_f + MN_STAGE;
    }

    #pragma unroll
    for (int mt = 0; mt < 2; mt++)
        #pragma unroll
        for (int j = 0; j < 8; j++) {
            int row = row0 + m_off + mt * 16 + (lane >> 2);
            int col = col0 + n_off + j * 8 + ((lane & 3) << 1);
            *reinterpret_cast<float2*>(out + (size_t)row * N_DIM + col)
                = make_float2(acc[mt][j][0], acc[mt][j][1]);
            *reinterpret_cast<float2*>(out + (size_t)(row + 8) * N_DIM + col)
                = make_float2(acc[mt][j][2], acc[mt][j][3]);
        }
}

// ---------------- launch -----------------------------------------------------
extern "C" void kernel_launch(void* const* d_in, const int* in_sizes, int n_in,
                              void* d_out, int out_size) {
    const float* x      = (const float*)d_in[0];
    const float* W      = (const float*)d_in[1];
    const float* lora_a = (const float*)d_in[2];
    const float* lora_b = (const float*)d_in[3];
    const int*   gl     = (const int*)d_in[4];
    const int n_groups  = in_sizes[4];
    float* out = (float*)d_out;

    cudaFuncSetAttribute(fused_main, cudaFuncAttributeMaxDynamicSharedMemorySize,
                         SMEM_BYTES);

    pre_kernel<<<CVT_BLK + 512, 256>>>(x, W, lora_a, lora_b);
    fused_main<<<64 + (N_DIM / 128) * (T_DIM / 128), 256, SMEM_BYTES>>>(
        gl, n_groups, out);
}

// round 15
// speedup vs baseline: 1.2567x; 1.0124x over previous
#include <cuda_runtime.h>
#include <cuda_fp16.h>
#include <cstdint>

#define T_DIM 8192
#define K_DIM 4096
#define N_DIM 4096
#define R_DIM 64
#define NGRP  8

// ---------------- static device scratch (alloc forbidden) -------------------
__device__ __half g_x16[(size_t)T_DIM * K_DIM];
__device__ __half g_w16[(size_t)N_DIM * K_DIM];
__device__ __half g_la16[(size_t)NGRP * R_DIM * K_DIM];
__device__ __half g_lb16[(size_t)NGRP * N_DIM * R_DIM];   // [g][n][r] transposed
__device__ __half g_sh16[(size_t)T_DIM * R_DIM];
__device__ int    g_flag;   // shrink-done counter (reset by pre_kernel)

// ---------------- asm helpers (base ISA only: sm_80-class) ------------------
__device__ __forceinline__ uint32_t smem_u32(const void* p) {
    uint32_t a;
    asm("{ .reg .u64 t; cvta.to.shared.u64 t, %1; cvt.u32.u64 %0, t; }"
        : "=r"(a) : "l"(p));
    return a;
}
#define CP16(dst, src) \
    asm volatile("cp.async.cg.shared.global [%0], [%1], 16;" :: "r"(dst), "l"(src))
#define CP_COMMIT() asm volatile("cp.async.commit_group;" ::: "memory")
#define CP_WAIT1()  asm volatile("cp.async.wait_group 1;"  ::: "memory")
#define CP_WAIT2()  asm volatile("cp.async.wait_group 2;"  ::: "memory")

#define LDSM4(d, addr) \
    asm volatile("ldmatrix.sync.aligned.m8n8.x4.shared.b16 {%0,%1,%2,%3}, [%4];" \
        : "=r"((d)[0]), "=r"((d)[1]), "=r"((d)[2]), "=r"((d)[3]) : "r"(addr))

#define MMA_F16(ac, a, b0, b1) \
    asm volatile("mma.sync.aligned.m16n8k16.row.col.f32.f16.f16.f32 " \
        "{%0,%1,%2,%3}, {%4,%5,%6,%7}, {%8,%9}, {%0,%1,%2,%3};" \
        : "+f"((ac)[0]), "+f"((ac)[1]), "+f"((ac)[2]), "+f"((ac)[3]) \
        : "r"((a)[0]), "r"((a)[1]), "r"((a)[2]), "r"((a)[3]), "r"(b0), "r"(b1))

// smem byte offset of 16B chunk (row, ch) within a tile of 128B rows (BK=64).
__device__ __forceinline__ uint32_t swz(int row, int ch) {
    return (uint32_t)((row << 7) | (((ch ^ (row & 7)) & 7) << 4));
}

__device__ __forceinline__ int find_group(const int* __restrict__ gl,
                                          int n_groups, int token) {
    int g = 0;
    while (g < n_groups - 1 && token >= gl[g]) g++;
    return g;
}

// ---------------- fused pre-pass: cvt(x,W,la) x4/thread + lorab transpose ---
#define NX4 ((size_t)T_DIM * K_DIM / 4)     // 8388608  (mult of 1024)
#define NW4 ((size_t)N_DIM * K_DIM / 4)     // 4194304  (mult of 1024)
#define NL4 ((size_t)NGRP * R_DIM * K_DIM / 4)  // 524288 (mult of 1024)
#define CVT_BLK ((unsigned)((NX4 + NW4 + NL4) / 1024))   // 12800

__global__ __launch_bounds__(256) void pre_kernel(
    const float* __restrict__ x, const float* __restrict__ W,
    const float* __restrict__ la, const float* __restrict__ lb)
{
    if (blockIdx.x == 0 && threadIdx.x == 0) g_flag = 0;
    if (blockIdx.x < CVT_BLK) {
        // 1024 float4s per block; region boundaries are multiples of 1024,
        // so a block never straddles regions.
        size_t base = (size_t)blockIdx.x * 1024;
        const float* src;
        __half2* dst;
        if (base < NX4) {
            src = x; dst = reinterpret_cast<__half2*>(g_x16);
        } else if (base < NX4 + NW4) {
            src = W; dst = reinterpret_cast<__half2*>(g_w16);
            base -= NX4;
        } else {
            src = la; dst = reinterpret_cast<__half2*>(g_la16);
            base -= NX4 + NW4;
        }
        // 4 independent float4s per thread (MLP=4), coalesced per step
        float4 v[4];
        #pragma unroll
        for (int it = 0; it < 4; it++)
            v[it] = reinterpret_cast<const float4*>(src)
                        [base + it * 256 + threadIdx.x];
        #pragma unroll
        for (int it = 0; it < 4; it++) {
            size_t j = base + it * 256 + threadIdx.x;
            dst[2 * j]     = __floats2half2_rn(v[it].x, v[it].y);
            dst[2 * j + 1] = __floats2half2_rn(v[it].z, v[it].w);
        }
    } else {
        // lorab transpose: [g][r][n] -> [g][n][r]
        __shared__ float t[64][65];
        int b = blockIdx.x - CVT_BLK;        // 0..511
        int g = b >> 6;
        int n0 = (b & 63) * 64;
        for (int idx = threadIdx.x; idx < 4096; idx += 256) {
            int r = idx >> 6, n = idx & 63;
            t[n][r] = lb[((size_t)g * R_DIM + r) * N_DIM + n0 + n];
        }
        __syncthreads();
        for (int idx = threadIdx.x; idx < 4096; idx += 256) {
            int n = idx >> 6, r = idx & 63;
            g_lb16[((size_t)g * N_DIM + n0 + n) * R_DIM + r] =
                __float2half_rn(t[n][r]);
        }
    }
}

// =============================================================================
// Fused main kernel (unchanged from R14 — the 731us config).
// Blocks 0..63: shrink tile; blocks 64..2111: GEMM tile. Flag handshake for
// the LoRA chunk.
// =============================================================================
#define SH_STAGE 24576
#define SH_CHUNKS (K_DIM / 64)       // 64
#define MN_STAGE 32768
#define MN_BASEC (K_DIM / 64)        // 64 base chunks
#define MN_CHUNKS (MN_BASEC + 1)     // + 1 LoRA chunk
#define SMEM_BYTES 98304             // == 4*SH_STAGE == 3*MN_STAGE

__global__ __launch_bounds__(256, 2) void fused_main(
    const int* __restrict__ gl, int n_groups, float* __restrict__ out)
{
    extern __shared__ char smem[];
    uint32_t sb = smem_u32(smem);
    int tid = threadIdx.x, lane = tid & 31, w = tid >> 5;

    if (blockIdx.x < 64) {
        // ------------------------- shrink path ------------------------------
        int m_off = (w & 3) * 32, n_off = (w >> 2) * 32;
        int row0 = blockIdx.x * 128;
        int g = find_group(gl, n_groups, row0);

        const __half* A = g_x16 + (size_t)row0 * K_DIM;
        const __half* B = g_la16 + (size_t)g * R_DIM * K_DIM;

        float acc[2][4][4];
        #pragma unroll
        for (int i = 0; i < 2; i++)
            #pragma unroll
            for (int j = 0; j < 4; j++)
                #pragma unroll
                for (int q = 0; q < 4; q++) acc[i][j][q] = 0.f;

        auto fill = [&](int s, int c) {
            uint32_t st = sb + s * SH_STAGE;
            #pragma unroll
            for (int it = 0; it < 6; it++) {
                int idx = tid + it * 256;
                if (idx < 1024) {
                    int row = idx >> 3, ch = idx & 7;
                    CP16(st + swz(row, ch),
                         A + (size_t)row * K_DIM + c * 64 + ch * 8);
                } else {
                    int u = idx - 1024;
                    int row = u >> 3, ch = u & 7;
                    CP16(st + 16384 + swz(row, ch),
                         B + (size_t)row * K_DIM + c * 64 + ch * 8);
                }
            }
        };

        fill(0, 0); CP_COMMIT();
        fill(1, 1); CP_COMMIT();
        fill(2, 2); CP_COMMIT();

        for (int c = 0; c < SH_CHUNKS; c++) {
            CP_WAIT2();
            __syncthreads();
            uint32_t st = sb + (c & 3) * SH_STAGE;
            #pragma unroll
            for (int ks = 0; ks < 4; ks++) {
                uint32_t aa[2][4], bb[2][4];
                #pragma unroll
                for (int mt = 0; mt < 2; mt++) {
                    int row = m_off + mt * 16 + (lane & 15);
                    int ch = ks * 2 + (lane >> 4);
                    LDSM4(aa[mt], st + swz(row, ch));
                }
                #pragma unroll
                for (int p = 0; p < 2; p++) {
                    int row = n_off + p * 16 + (lane & 15);
                    int ch = ks * 2 + (lane >> 4);
                    LDSM4(bb[p], st + 16384 + swz(row, ch));
                }
                #pragma unroll
                for (int mt = 0; mt < 2; mt++)
                    #pragma unroll
                    for (int p = 0; p < 2; p++) {
                        MMA_F16(acc[mt][2 * p],     aa[mt], bb[p][0], bb[p][2]);
                        MMA_F16(acc[mt][2 * p + 1], aa[mt], bb[p][1], bb[p][3]);
                    }
            }
            if (c + 3 < SH_CHUNKS) fill((c + 3) & 3, c + 3);
            CP_COMMIT();
        }

        #pragma unroll
        for (int mt = 0; mt < 2; mt++)
            #pragma unroll
            for (int j = 0; j < 4; j++) {
                int row = row0 + m_off + mt * 16 + (lane >> 2);
                int col = n_off + j * 8 + ((lane & 3) << 1);
                *reinterpret_cast<__half2*>(g_sh16 + (size_t)row * R_DIM + col)
                    = __floats2half2_rn(acc[mt][j][0], acc[mt][j][1]);
                *reinterpret_cast<__half2*>(g_sh16 + (size_t)(row + 8) * R_DIM + col)
                    = __floats2half2_rn(acc[mt][j][2], acc[mt][j][3]);
            }
        __syncthreads();
        __threadfence();                     // release g_sh16 writes
        if (tid == 0) atomicAdd(&g_flag, 1);
        return;
    }

    // ----------------------------- GEMM path --------------------------------
    int b = blockIdx.x - 64;
    int col0 = (b & 31) * 128;
    int row0 = (b >> 5) * 128;
    int m_off = (w & 3) * 32, n_off = (w >> 2) * 64;
    int g = find_group(gl, n_groups, row0);

    float acc[2][8][4];
    #pragma unroll
    for (int i = 0; i < 2; i++)
        #pragma unroll
        for (int j = 0; j < 8; j++)
            #pragma unroll
            for (int q = 0; q < 4; q++) acc[i][j][q] = 0.f;

    // ---- hoisted LDSM addressing ----
    const int lr  = lane & 15;
    const int par = lane >> 4;
    const int r   = lr & 7;
    const uint32_t pbit = (uint32_t)((par ^ (r & 1)) << 4);
    const int rk = (r >> 1) & 3;
    uint32_t k_off[4];
    #pragma unroll
    for (int ks = 0; ks < 4; ks++) k_off[ks] = (uint32_t)(((ks ^ rk) & 3) << 5);
    uint32_t a_cst[2], b_cst[4];
    #pragma unroll
    for (int mt = 0; mt < 2; mt++)
        a_cst[mt] = (uint32_t)((m_off + mt * 16 + lr) << 7) + pbit;
    #pragma unroll
    for (int p = 0; p < 4; p++)
        b_cst[p] = 16384u + (uint32_t)((n_off + p * 16 + lr) << 7) + pbit;

    // ---- hoisted fill addressing (8 CP16s/thread: 4 A + 4 B) ----
    uint32_t s_off[8];
    int      g_off[8];
    #pragma unroll
    for (int it = 0; it < 8; it++) {
        int idx = tid + it * 256;
        if (idx < 1024) {
            int row = idx >> 3, ch = idx & 7;
            s_off[it] = swz(row, ch);
            g_off[it] = row * K_DIM + ch * 8;
        } else {
            int u = idx - 1024;
            int row = u >> 3, ch = u & 7;
            s_off[it] = 16384u + swz(row, ch);
            g_off[it] = row * K_DIM + ch * 8;
        }
    }
    const __half* pAf = g_x16 + (size_t)row0 * K_DIM;
    const __half* pBf = g_w16 + (size_t)col0 * K_DIM;

    auto fill_main = [&](uint32_t st) {
        #pragma unroll
        for (int it = 0; it < 4; it++)
            CP16(st + s_off[it], pAf + g_off[it]);
        #pragma unroll
        for (int it = 4; it < 8; it++)
            CP16(st + s_off[it], pBf + g_off[it]);
        pAf += 64; pBf += 64;
    };
    auto fill_lora = [&](uint32_t st) {
        const __half* pA = g_sh16 + (size_t)row0 * R_DIM;
        const __half* pB = g_lb16 + ((size_t)g * N_DIM + col0) * R_DIM;
        #pragma unroll
        for (int it = 0; it < 8; it++) {
            int idx = tid + it * 256;
            if (idx < 1024) {
                int row = idx >> 3, ch = idx & 7;
                CP16(st + swz(row, ch), pA + row * R_DIM + ch * 8);
            } else {
                int u = idx - 1024;
                int row = u >> 3, ch = u & 7;
                CP16(st + 16384u + swz(row, ch), pB + row * R_DIM + ch * 8);
            }
        }
    };

    fill_main(sb);             CP_COMMIT();
    fill_main(sb + MN_STAGE);  CP_COMMIT();

    uint32_t st_c = sb;
    uint32_t st_f = sb + 2u * MN_STAGE;
    const uint32_t st_top = sb + 2u * MN_STAGE;

    for (int c = 0; c < MN_CHUNKS; c++) {
        CP_WAIT1();
        __syncthreads();
        #pragma unroll
        for (int ks = 0; ks < 4; ks++) {
            uint32_t aa[2][4], bb[4][4];
            #pragma unroll
            for (int mt = 0; mt < 2; mt++)
                LDSM4(aa[mt], st_c + a_cst[mt] + k_off[ks]);
            #pragma unroll
            for (int p = 0; p < 4; p++)
                LDSM4(bb[p], st_c + b_cst[p] + k_off[ks]);
            #pragma unroll
            for (int mt = 0; mt < 2; mt++)
                #pragma unroll
                for (int p = 0; p < 4; p++) {
                    MMA_F16(acc[mt][2 * p],     aa[mt], bb[p][0], bb[p][2]);
                    MMA_F16(acc[mt][2 * p + 1], aa[mt], bb[p][1], bb[p][3]);
                }
        }
        if (c + 2 < MN_BASEC) {
            fill_main(st_f);
        } else if (c + 2 == MN_BASEC) {
            if (tid == 0) {
                while (atomicAdd(&g_flag, 0) < 64) { }
            }
            __syncthreads();
            __threadfence();
            fill_lora(st_f);
        }
        CP_COMMIT();
        st_c = (st_c == st_top) ? sb : st_c + MN_STAGE;
        st_f = (st_f == st_top) ? sb : st_f + MN_STAGE;
    }

    #pragma unroll
    for (int mt = 0; mt < 2; mt++)
        #pragma unroll
        for (int j = 0; j < 8; j++) {
            int row = row0 + m_off + mt * 16 + (lane >> 2);
            int col = col0 + n_off + j * 8 + ((lane & 3) << 1);
            *reinterpret_cast<float2*>(out + (size_t)row * N_DIM + col)
                = make_float2(acc[mt][j][0], acc[mt][j][1]);
            *reinterpret_cast<float2*>(out + (size_t)(row + 8) * N_DIM + col)
                = make_float2(acc[mt][j][2], acc[mt][j][3]);
        }
}

// ---------------- launch -----------------------------------------------------
extern "C" void kernel_launch(void* const* d_in, const int* in_sizes, int n_in,
                              void* d_out, int out_size) {
    const float* x      = (const float*)d_in[0];
    const float* W      = (const float*)d_in[1];
    const float* lora_a = (const float*)d_in[2];
    const float* lora_b = (const float*)d_in[3];
    const int*   gl     = (const int*)d_in[4];
    const int n_groups  = in_sizes[4];
    float* out = (float*)d_out;

    cudaFuncSetAttribute(fused_main, cudaFuncAttributeMaxDynamicSharedMemorySize,
                         SMEM_BYTES);

    pre_kernel<<<CVT_BLK + 512, 256>>>(x, W, lora_a, lora_b);
    fused_main<<<64 + (N_DIM / 128) * (T_DIM / 128), 256, SMEM_BYTES>>>(
        gl, n_groups, out);
}